// round 16
// baseline (speedup 1.0000x reference)
#include <cuda_runtime.h>
#include <math.h>
#include <stdint.h>

#define N_NODES 50000
#define E_EDGES 800000
#define D_DIM   128
#define A_DIM   5

// Scratch (no allocations allowed in kernel_launch)
__device__ float g_node_px[N_NODES * D_DIM];       // node_px [N,128]
__device__ float g_s[N_NODES * 16];                // s_src[5] @0, s_dst[5] @8
__device__ float g_wgt[(N_NODES + 8) * 8];         // node softmax weights (5 used)
__device__ float g_bsum[(N_NODES + 128) * 8];      // b-sum per node, 8-stride

__device__ __forceinline__ uint32_t f2tf(float f) {
    uint32_t r; asm("cvt.rna.tf32.f32 %0, %1;" : "=r"(r) : "f"(f)); return r;
}

__device__ __forceinline__ void mma_tf32(float* d, const uint32_t* a, const uint32_t* b) {
    asm volatile("mma.sync.aligned.m16n8k8.row.col.f32.tf32.tf32.f32 "
        "{%0,%1,%2,%3}, {%4,%5,%6,%7}, {%8,%9}, {%0,%1,%2,%3};"
        : "+f"(d[0]), "+f"(d[1]), "+f"(d[2]), "+f"(d[3])
        : "r"(a[0]), "r"(a[1]), "r"(a[2]), "r"(a[3]), "r"(b[0]), "r"(b[1]));
}

// ---------------------------------------------------------------------------
// Kernel 1: per-node precompute, SINGLE PASS (proven 21.8us). Emits g_s,
// g_wgt, zeros g_bsum. px is produced inside the edge kernel.
// ---------------------------------------------------------------------------
#define XT 33

__global__ __launch_bounds__(256) void node_pre_kernel(
    const float* __restrict__ x,
    const float* __restrict__ attn_w,
    const float* __restrict__ attn_b,
    const float* __restrict__ w_w)
{
    __shared__ float shT[15 * D_DIM];     // attnT | wsT | wdT
    __shared__ float sAB[8];
    __shared__ float sx[256 * XT];        // one 256x32 chunk

    int tid = threadIdx.x;
    int row0 = blockIdx.x * 256;

    for (int i = tid; i < 640; i += 256) {
        int a = i >> 7, d = i & 127;
        shT[a * 128 + d]        = attn_w[d * A_DIM + a];
        shT[640 + a * 128 + d]  = w_w[d * A_DIM + a];
        shT[1280 + a * 128 + d] = w_w[(128 + d) * A_DIM + a];
    }
    if (tid < A_DIM) sAB[tid] = attn_b[tid];

    int n = row0 + tid;
    bool act = (n < N_NODES);

    float aA[A_DIM], aS[A_DIM], aD[A_DIM];
#pragma unroll
    for (int c = 0; c < A_DIM; c++) { aA[c] = 0.f; aS[c] = 0.f; aD[c] = 0.f; }

#pragma unroll 1
    for (int ch = 0; ch < 4; ch++) {
        __syncthreads();
        for (int idx = tid; idx < 2048; idx += 256) {      // 2048 float4
            int r = idx >> 3, c4 = (idx & 7) << 2;
            int n2 = row0 + r;
            if (n2 < N_NODES) {
                float4 v = __ldg(reinterpret_cast<const float4*>(
                    &x[(size_t)n2 * D_DIM + ch * 32 + c4]));
                float* d = &sx[r * XT + c4];
                d[0] = v.x; d[1] = v.y; d[2] = v.z; d[3] = v.w;
            }
        }
        __syncthreads();
        if (act) {
            const float* xr = &sx[tid * XT];
#pragma unroll
            for (int j4 = 0; j4 < 8; j4++) {
                int col = ch * 32 + j4 * 4;
                float x0 = xr[j4*4], x1 = xr[j4*4+1], x2 = xr[j4*4+2], x3 = xr[j4*4+3];
#pragma unroll
                for (int c = 0; c < A_DIM; c++) {
                    float4 wa = *reinterpret_cast<const float4*>(&shT[c * 128 + col]);
                    float4 ws = *reinterpret_cast<const float4*>(&shT[640 + c * 128 + col]);
                    float4 wd = *reinterpret_cast<const float4*>(&shT[1280 + c * 128 + col]);
                    aA[c] = fmaf(x0, wa.x, fmaf(x1, wa.y, fmaf(x2, wa.z, fmaf(x3, wa.w, aA[c]))));
                    aS[c] = fmaf(x0, ws.x, fmaf(x1, ws.y, fmaf(x2, ws.z, fmaf(x3, ws.w, aS[c]))));
                    aD[c] = fmaf(x0, wd.x, fmaf(x1, wd.y, fmaf(x2, wd.z, fmaf(x3, wd.w, aD[c]))));
                }
            }
        }
    }

    if (act) {
        float wgt[A_DIM];
        float m = -1e30f;
#pragma unroll
        for (int c = 0; c < A_DIM; c++) { wgt[c] = aA[c] + sAB[c]; m = fmaxf(m, wgt[c]); }
        float ssum = 0.f;
#pragma unroll
        for (int c = 0; c < A_DIM; c++) { wgt[c] = __expf(wgt[c] - m); ssum += wgt[c]; }
        float inv = 1.0f / ssum;
#pragma unroll
        for (int c = 0; c < A_DIM; c++) wgt[c] *= inv;

        float4 sv = {aS[0], aS[1], aS[2], aS[3]};
        float4 dv = {aD[0], aD[1], aD[2], aD[3]};
        *reinterpret_cast<float4*>(&g_s[n * 16])     = sv;
        g_s[n * 16 + 4]                              = aS[4];
        *reinterpret_cast<float4*>(&g_s[n * 16 + 8]) = dv;
        g_s[n * 16 + 12]                             = aD[4];
        float4 wv = {wgt[0], wgt[1], wgt[2], wgt[3]};
        *reinterpret_cast<float4*>(&g_wgt[(size_t)n * 8]) = wv;
        g_wgt[(size_t)n * 8 + 4]                          = wgt[4];
        float4 z = {0.f, 0.f, 0.f, 0.f};
        *reinterpret_cast<float4*>(&g_bsum[(size_t)n * 8])     = z;
        *reinterpret_cast<float4*>(&g_bsum[(size_t)n * 8 + 4]) = z;
    }
}

// ---------------------------------------------------------------------------
// Kernel 2: edges + hidden px pass (R15, kept verbatim).
// ---------------------------------------------------------------------------
__global__ __launch_bounds__(256) void edge_kernel(
    const int* __restrict__ edge_index,
    const float* __restrict__ anchor_edge,
    const float* __restrict__ w_b,
    const float* __restrict__ x,
    const float* __restrict__ anchor_node,
    float* __restrict__ out_edge)
{
    int tid  = threadIdx.x;
    int lane = tid & 31;
    int wid  = tid >> 5;

    float4 ae[A_DIM];
    float  wb[A_DIM];
#pragma unroll
    for (int c = 0; c < A_DIM; c++) {
        ae[c] = __ldg(&reinterpret_cast<const float4*>(anchor_edge + c * D_DIM)[lane]);
        wb[c] = __ldg(&w_b[c]);
    }
    uint64_t aeXY[A_DIM], aeZW[A_DIM];
#pragma unroll
    for (int c = 0; c < A_DIM; c++) {
        asm("mov.b64 %0, {%1, %2};" : "=l"(aeXY[c]) : "f"(ae[c].x), "f"(ae[c].y));
        asm("mov.b64 %0, {%1, %2};" : "=l"(aeZW[c]) : "f"(ae[c].z), "f"(ae[c].w));
    }

    int e = blockIdx.x * 256 + tid;
    int src = edge_index[e];
    int dst = edge_index[E_EDGES + e];

    float4 s03 = *reinterpret_cast<const float4*>(&g_s[src * 16]);
    float  s4  = g_s[src * 16 + 4];
    float4 d03 = *reinterpret_cast<const float4*>(&g_s[dst * 16 + 8]);
    float  d4  = g_s[dst * 16 + 12];

    float b[A_DIM];
    b[0] = s03.x + d03.x + wb[0];
    b[1] = s03.y + d03.y + wb[1];
    b[2] = s03.z + d03.z + wb[2];
    b[3] = s03.w + d03.w + wb[3];
    b[4] = s4    + d4    + wb[4];

    float m = -1e30f;
#pragma unroll
    for (int c = 0; c < A_DIM; c++) {
        b[c] = (b[c] > 0.f) ? b[c] : 0.01f * b[c];   // leaky_relu
        m = fmaxf(m, b[c]);
    }
    float ssum = 0.f;
#pragma unroll
    for (int c = 0; c < A_DIM; c++) { b[c] = __expf(b[c] - m); ssum += b[c]; }
    float inv = 1.0f / ssum;
#pragma unroll
    for (int c = 0; c < A_DIM; c++) b[c] *= inv;

    {
        float* ps = &g_bsum[(size_t)src * 8];
        float* pd = &g_bsum[(size_t)dst * 8];
        asm volatile("red.global.add.v4.f32 [%0], {%1,%2,%3,%4};"
                     :: "l"(ps), "f"(b[0]), "f"(b[1]), "f"(b[2]), "f"(b[3]) : "memory");
        asm volatile("red.global.add.f32 [%0+16], %1;"
                     :: "l"(ps), "f"(b[4]) : "memory");
        asm volatile("red.global.add.v4.f32 [%0], {%1,%2,%3,%4};"
                     :: "l"(pd), "f"(b[0]), "f"(b[1]), "f"(b[2]), "f"(b[3]) : "memory");
        asm volatile("red.global.add.f32 [%0+16], %1;"
                     :: "l"(pd), "f"(b[4]) : "memory");
    }

    size_t ebase = (size_t)blockIdx.x * 256 + wid * 32;
#pragma unroll 4
    for (int le = 0; le < 32; le++) {
        uint64_t oxy, ozw;
        {
            float bc = __shfl_sync(0xffffffffu, b[4], le);
            uint64_t bb;
            asm("mov.b64 %0, {%1, %1};" : "=l"(bb) : "f"(bc));
            asm("mul.rn.f32x2 %0, %1, %2;" : "=l"(oxy) : "l"(bb), "l"(aeXY[4]));
            asm("mul.rn.f32x2 %0, %1, %2;" : "=l"(ozw) : "l"(bb), "l"(aeZW[4]));
        }
#pragma unroll
        for (int c = 0; c < 4; c++) {
            float bc = __shfl_sync(0xffffffffu, b[c], le);
            uint64_t bb;
            asm("mov.b64 %0, {%1, %1};" : "=l"(bb) : "f"(bc));
            asm("fma.rn.f32x2 %0, %1, %2, %3;" : "=l"(oxy) : "l"(bb), "l"(aeXY[c]), "l"(oxy));
            asm("fma.rn.f32x2 %0, %1, %2, %3;" : "=l"(ozw) : "l"(bb), "l"(aeZW[c]), "l"(ozw));
        }
        float4 o;
        asm("mov.b64 {%0, %1}, %2;" : "=f"(o.x), "=f"(o.y) : "l"(oxy));
        asm("mov.b64 {%0, %1}, %2;" : "=f"(o.z), "=f"(o.w) : "l"(ozw));
        __stcs(&reinterpret_cast<float4*>(out_edge + (ebase + le) * D_DIM)[lane], o);
    }

    // ---- hidden px pass: nodes [16*bid, 16*bid+16) ----
    {
        int nbase = blockIdx.x * 16;
        int c4 = (tid & 31) << 2;
        float4 a0 = __ldg(reinterpret_cast<const float4*>(&anchor_node[0 * D_DIM + c4]));
        float4 a1 = __ldg(reinterpret_cast<const float4*>(&anchor_node[1 * D_DIM + c4]));
        float4 a2 = __ldg(reinterpret_cast<const float4*>(&anchor_node[2 * D_DIM + c4]));
        float4 a3 = __ldg(reinterpret_cast<const float4*>(&anchor_node[3 * D_DIM + c4]));
        float4 a4 = __ldg(reinterpret_cast<const float4*>(&anchor_node[4 * D_DIM + c4]));
#pragma unroll
        for (int k = 0; k < 2; k++) {
            int ln = (tid >> 5) + k * 8;
            int n2 = nbase + ln;
            if (n2 < N_NODES) {
                float4 w03 = __ldg(reinterpret_cast<const float4*>(&g_wgt[(size_t)n2 * 8]));
                float  w4  = __ldg(&g_wgt[(size_t)n2 * 8 + 4]);
                float4 xv = __ldg(reinterpret_cast<const float4*>(&x[(size_t)n2 * D_DIM + c4]));
                xv.x = fmaf(w03.x,a0.x, fmaf(w03.y,a1.x, fmaf(w03.z,a2.x, fmaf(w03.w,a3.x, fmaf(w4,a4.x, xv.x)))));
                xv.y = fmaf(w03.x,a0.y, fmaf(w03.y,a1.y, fmaf(w03.z,a2.y, fmaf(w03.w,a3.y, fmaf(w4,a4.y, xv.y)))));
                xv.z = fmaf(w03.x,a0.z, fmaf(w03.y,a1.z, fmaf(w03.z,a2.z, fmaf(w03.w,a3.z, fmaf(w4,a4.z, xv.z)))));
                xv.w = fmaf(w03.x,a0.w, fmaf(w03.y,a1.w, fmaf(w03.z,a2.w, fmaf(w03.w,a3.w, fmaf(w4,a4.w, xv.w)))));
                *reinterpret_cast<float4*>(&g_node_px[(size_t)n2 * D_DIM + c4]) = xv;
            }
        }
    }
}

// ---------------------------------------------------------------------------
// Kernel 3: fused node-side GEMMs, RESTRUCTURED: 64 rows/block, 2 CTAs/SM,
// double-buffered weight chunks (ONE barrier per chunk). GEMM order:
//   GEMM3 (psum@int_w)  chunks 0-3   acc3
//   GEMM1 ([px|agg]@cd1) chunks 4-11 acc1
//   h = relu(acc1+b1) -> sAG (agg dead)
//   GEMM2 (h@cd2)        chunks 12-15 acc2
// ---------------------------------------------------------------------------
#define TMR 64
#define SP  132
#define WP  136
#define SMEM_FLOATS (2 * TMR * SP + 2 * 32 * WP)
#define SMEM_BYTES  (SMEM_FLOATS * 4)

__device__ __forceinline__ void w_preload(const float* __restrict__ W, int kb,
                                          int tid, float4 w[4]) {
#pragma unroll
    for (int j = 0; j < 4; j++) {
        int i = tid + j * 256;
        int r = i >> 5, c4 = (i & 31) << 2;
        w[j] = __ldg(reinterpret_cast<const float4*>(&W[(kb + r) * 128 + c4]));
    }
}

__device__ __forceinline__ void w_commit(float* __restrict__ sW, int tid,
                                         const float4 w[4]) {
#pragma unroll
    for (int j = 0; j < 4; j++) {
        int i = tid + j * 256;
        int r = i >> 5, c4 = (i & 31) << 2;
        float4 t;
        t.x = __uint_as_float(f2tf(w[j].x));
        t.y = __uint_as_float(f2tf(w[j].y));
        t.z = __uint_as_float(f2tf(w[j].z));
        t.w = __uint_as_float(f2tf(w[j].w));
        *reinterpret_cast<float4*>(&sW[r * WP + c4]) = t;
    }
}

__device__ __forceinline__ void chunk_pt2(
    const float* __restrict__ A, int kof, const float* __restrict__ sW,
    int rbase, int nbase, int g, int tg, float acc[2][4][4])
{
#pragma unroll
    for (int ks = 0; ks < 4; ks++) {
        int k0 = ks * 8;
        uint32_t afr[2][4];
#pragma unroll
        for (int mi = 0; mi < 2; mi++) {
            const float* ap = &A[(rbase + mi * 16 + g) * SP + kof + k0 + tg];
            afr[mi][0] = __float_as_uint(ap[0]);
            afr[mi][1] = __float_as_uint(ap[8 * SP]);
            afr[mi][2] = __float_as_uint(ap[4]);
            afr[mi][3] = __float_as_uint(ap[8 * SP + 4]);
        }
        uint32_t bfr[4][2];
#pragma unroll
        for (int ni = 0; ni < 4; ni++) {
            const float* bp = &sW[(k0 + tg) * WP + nbase + ni * 8 + g];
            bfr[ni][0] = __float_as_uint(bp[0]);
            bfr[ni][1] = __float_as_uint(bp[4 * WP]);
        }
#pragma unroll
        for (int mi = 0; mi < 2; mi++)
#pragma unroll
            for (int ni = 0; ni < 4; ni++)
                mma_tf32(acc[mi][ni], afr[mi], bfr[ni]);
    }
}

__device__ __forceinline__ void chunk_sum2(
    const float* __restrict__ A0, const float* __restrict__ A1, int kof,
    const float* __restrict__ sW, int rbase, int nbase, int g, int tg,
    float acc[2][4][4])
{
#pragma unroll
    for (int ks = 0; ks < 4; ks++) {
        int k0 = ks * 8;
        uint32_t afr[2][4];
#pragma unroll
        for (int mi = 0; mi < 2; mi++) {
            int off = (rbase + mi * 16 + g) * SP + kof + k0 + tg;
            afr[mi][0] = f2tf(A0[off]            + A1[off]);
            afr[mi][1] = f2tf(A0[off + 8 * SP]   + A1[off + 8 * SP]);
            afr[mi][2] = f2tf(A0[off + 4]        + A1[off + 4]);
            afr[mi][3] = f2tf(A0[off + 8*SP + 4] + A1[off + 8*SP + 4]);
        }
        uint32_t bfr[4][2];
#pragma unroll
        for (int ni = 0; ni < 4; ni++) {
            const float* bp = &sW[(k0 + tg) * WP + nbase + ni * 8 + g];
            bfr[ni][0] = __float_as_uint(bp[0]);
            bfr[ni][1] = __float_as_uint(bp[4 * WP]);
        }
#pragma unroll
        for (int mi = 0; mi < 2; mi++)
#pragma unroll
            for (int ni = 0; ni < 4; ni++)
                mma_tf32(acc[mi][ni], afr[mi], bfr[ni]);
    }
}

__global__ __launch_bounds__(256, 2) void node_post_kernel(
    const float* __restrict__ anchor_edge,
    const float* __restrict__ cd1_w, const float* __restrict__ cd1_b,
    const float* __restrict__ cd2_w, const float* __restrict__ cd2_b,
    const float* __restrict__ int_w, const float* __restrict__ int_b,
    float* __restrict__ out_final)
{
    extern __shared__ float smem[];
    float* sPX = smem;                  // [64][SP] tf32(px)
    float* sAG = sPX + TMR * SP;        // [64][SP] tf32(agg); later tf32(h); later final-partial
    float* sW0 = sAG + TMR * SP;        // [32][WP]
    float* sW1 = sW0 + 32 * WP;         // [32][WP]

    int tid = threadIdx.x;
    int row0 = blockIdx.x * TMR;

    // staging scratch lives in sW0: bsum [64*8] @0, anchor_edge [640] @512
    for (int i = tid; i < TMR * 8; i += 256) {
        int n = row0 + (i >> 3);
        sW0[i] = (n < N_NODES) ? g_bsum[(size_t)n * 8 + (i & 7)] : 0.f;
    }
    for (int i = tid; i < A_DIM * D_DIM; i += 256) sW0[TMR * 8 + i] = anchor_edge[i];
    __syncthreads();

    for (int idx = tid; idx < TMR * D_DIM; idx += 256) {
        int r = idx >> 7, c = idx & 127;
        int n = row0 + r;
        float px = (n < N_NODES) ? g_node_px[(size_t)n * D_DIM + c] : 0.f;
        float ag = 0.f;
#pragma unroll
        for (int a = 0; a < A_DIM; a++)
            ag = fmaf(sW0[r * 8 + a], sW0[TMR * 8 + a * D_DIM + c], ag);
        sPX[r * SP + c] = __uint_as_float(f2tf(px));
        sAG[r * SP + c] = __uint_as_float(f2tf(ag));
    }
    __syncthreads();   // scratch reads done; sW0 reusable

    int lane = tid & 31, wid = tid >> 5;
    int wm = wid >> 2, wn = wid & 3;     // 2 x 4 warp grid, warp tile 32x32
    int g = lane >> 2, tg = lane & 3;
    int rbase = wm * 32;
    int nbase = wn * 32;

    // chunk schedule: 0-3 int_w (GEMM3), 4-11 cd1_w (GEMM1), 12-15 cd2_w (GEMM2)
    float4 wreg[4];
    w_preload(int_w, 0, tid, wreg);
    w_commit(sW0, tid, wreg);
    w_preload(int_w, 32, tid, wreg);     // chunk 1
    __syncthreads();

    float acc3[2][4][4], acc1[2][4][4], acc2[2][4][4];
#pragma unroll
    for (int mi = 0; mi < 2; mi++)
#pragma unroll
        for (int ni = 0; ni < 4; ni++)
#pragma unroll
            for (int q = 0; q < 4; q++) { acc3[mi][ni][q] = 0.f; acc1[mi][ni][q] = 0.f; acc2[mi][ni][q] = 0.f; }

#pragma unroll 1
    for (int c = 0; c < 16; c++) {
        float* bufs[2] = {sW0, sW1};
        // commit chunk c+1 (already in wreg), preload chunk c+2
        if (c < 15) {
            w_commit(bufs[(c + 1) & 1], tid, wreg);
            int k2 = c + 2;
            if (k2 < 4)        w_preload(int_w, k2 * 32, tid, wreg);
            else if (k2 < 12)  w_preload(cd1_w, (k2 - 4) * 32, tid, wreg);
            else if (k2 < 16)  w_preload(cd2_w, (k2 - 12) * 32, tid, wreg);
        }
        const float* sWc = bufs[c & 1];
        if (c < 4)        chunk_sum2(sPX, sAG, c * 32, sWc, rbase, nbase, g, tg, acc3);
        else if (c < 8)   chunk_pt2(sPX, (c - 4) * 32, sWc, rbase, nbase, g, tg, acc1);
        else if (c < 12)  chunk_pt2(sAG, (c - 8) * 32, sWc, rbase, nbase, g, tg, acc1);
        else              chunk_pt2(sAG, (c - 12) * 32, sWc, rbase, nbase, g, tg, acc2);
        __syncthreads();

        if (c == 11) {
            // h = tf32(relu(acc1 + b1)) -> sAG (agg fully consumed)
#pragma unroll
            for (int mi = 0; mi < 2; mi++)
#pragma unroll
                for (int ni = 0; ni < 4; ni++) {
                    int r0 = rbase + mi * 16 + g;
                    int c0 = nbase + ni * 8 + 2 * tg;
                    float b0v = cd1_b[c0], b1v = cd1_b[c0 + 1];
                    sAG[r0 * SP + c0]           = __uint_as_float(f2tf(fmaxf(acc1[mi][ni][0] + b0v, 0.f)));
                    sAG[r0 * SP + c0 + 1]       = __uint_as_float(f2tf(fmaxf(acc1[mi][ni][1] + b1v, 0.f)));
                    sAG[(r0 + 8) * SP + c0]     = __uint_as_float(f2tf(fmaxf(acc1[mi][ni][2] + b0v, 0.f)));
                    sAG[(r0 + 8) * SP + c0 + 1] = __uint_as_float(f2tf(fmaxf(acc1[mi][ni][3] + b1v, 0.f)));
                }
            __syncthreads();
        }
    }

    // final-partial = sigmoid(acc2+b2) * (acc3+int_b) -> sAG (h consumed)
#pragma unroll
    for (int mi = 0; mi < 2; mi++)
#pragma unroll
        for (int ni = 0; ni < 4; ni++) {
            int r0 = rbase + mi * 16 + g;
            int c0 = nbase + ni * 8 + 2 * tg;
            float bc0 = cd2_b[c0], bc1 = cd2_b[c0 + 1];
            float bi0 = int_b[c0], bi1 = int_b[c0 + 1];
#pragma unroll
            for (int h = 0; h < 2; h++) {
                int rr = r0 + h * 8;
                float cs0 = 1.0f / (1.0f + __expf(-(acc2[mi][ni][2*h]   + bc0)));
                float cs1 = 1.0f / (1.0f + __expf(-(acc2[mi][ni][2*h+1] + bc1)));
                sAG[rr * SP + c0]     = cs0 * (acc3[mi][ni][2*h]   + bi0);
                sAG[rr * SP + c0 + 1] = cs1 * (acc3[mi][ni][2*h+1] + bi1);
            }
        }
    __syncthreads();

    // out = staged tf32(px) + final-partial, coalesced float4
    for (int idx = tid; idx < TMR * 32; idx += 256) {
        int r = idx >> 5, c4 = (idx & 31) << 2;
        int n = row0 + r;
        if (n < N_NODES) {
            const float* pp = &sPX[r * SP + c4];
            const float* hp = &sAG[r * SP + c4];
            float4 o = {pp[0] + hp[0], pp[1] + hp[1], pp[2] + hp[2], pp[3] + hp[3]};
            *reinterpret_cast<float4*>(&out_final[(size_t)n * D_DIM + c4]) = o;
        }
    }
}

// ---------------------------------------------------------------------------
extern "C" void kernel_launch(void* const* d_in, const int* in_sizes, int n_in,
                              void* d_out, int out_size)
{
    const float* x           = (const float*)d_in[0];
    const float* anchor_node = (const float*)d_in[1];
    const float* attn_w      = (const float*)d_in[2];
    const float* attn_b      = (const float*)d_in[3];
    const float* anchor_edge = (const float*)d_in[4];
    const float* w_w         = (const float*)d_in[5];
    const float* w_b         = (const float*)d_in[6];
    const float* cd1_w       = (const float*)d_in[7];
    const float* cd1_b       = (const float*)d_in[8];
    const float* cd2_w       = (const float*)d_in[9];
    const float* cd2_b       = (const float*)d_in[10];
    const float* int_w       = (const float*)d_in[11];
    const float* int_b       = (const float*)d_in[12];
    const int*   edge_index  = (const int*)d_in[13];
    float* outp = (float*)d_out;   // [0, N*D) = final_x, [N*D, ...) = edge_prompt

    node_pre_kernel<<<(N_NODES + 255) / 256, 256>>>(x, attn_w, attn_b, w_w);
    edge_kernel<<<E_EDGES / 256, 256>>>(edge_index, anchor_edge, w_b, x, anchor_node,
                                        outp + (size_t)N_NODES * D_DIM);
    cudaFuncSetAttribute(node_post_kernel,
                         cudaFuncAttributeMaxDynamicSharedMemorySize, SMEM_BYTES);
    node_post_kernel<<<(N_NODES + TMR - 1) / TMR, 256, SMEM_BYTES>>>(
        anchor_edge, cd1_w, cd1_b, cd2_w, cd2_b, int_w, int_b, outp);
}

// round 17
// speedup vs baseline: 1.0483x; 1.0483x over previous
#include <cuda_runtime.h>
#include <math.h>
#include <stdint.h>

#define N_NODES 50000
#define E_EDGES 800000
#define D_DIM   128
#define A_DIM   5

// Scratch (no allocations allowed in kernel_launch)
__device__ float g_node_px[N_NODES * D_DIM];       // node_px [N,128]
__device__ float g_s[N_NODES * 16];                // s_src[5] @0, s_dst[5] @8
__device__ float g_wgt[(N_NODES + 8) * 8];         // node softmax weights (5 used)
__device__ float g_bsum[(N_NODES + 128) * 8];      // b-sum per node, 8-stride
__device__ float g_b[(size_t)E_EDGES * 8];         // per-edge b vector (5 used)

__device__ __forceinline__ uint32_t f2tf(float f) {
    uint32_t r; asm("cvt.rna.tf32.f32 %0, %1;" : "=r"(r) : "f"(f)); return r;
}

__device__ __forceinline__ void mma_tf32(float* d, const uint32_t* a, const uint32_t* b) {
    asm volatile("mma.sync.aligned.m16n8k8.row.col.f32.tf32.tf32.f32 "
        "{%0,%1,%2,%3}, {%4,%5,%6,%7}, {%8,%9}, {%0,%1,%2,%3};"
        : "+f"(d[0]), "+f"(d[1]), "+f"(d[2]), "+f"(d[3])
        : "r"(a[0]), "r"(a[1]), "r"(a[2]), "r"(a[3]), "r"(b[0]), "r"(b[1]));
}

// ---------------------------------------------------------------------------
// Kernel 1: per-node precompute, SINGLE PASS (proven ~21.5us).
// ---------------------------------------------------------------------------
#define XT 33

__global__ __launch_bounds__(256) void node_pre_kernel(
    const float* __restrict__ x,
    const float* __restrict__ attn_w,
    const float* __restrict__ attn_b,
    const float* __restrict__ w_w)
{
    __shared__ float shT[15 * D_DIM];     // attnT | wsT | wdT
    __shared__ float sAB[8];
    __shared__ float sx[256 * XT];        // one 256x32 chunk

    int tid = threadIdx.x;
    int row0 = blockIdx.x * 256;

    for (int i = tid; i < 640; i += 256) {
        int a = i >> 7, d = i & 127;
        shT[a * 128 + d]        = attn_w[d * A_DIM + a];
        shT[640 + a * 128 + d]  = w_w[d * A_DIM + a];
        shT[1280 + a * 128 + d] = w_w[(128 + d) * A_DIM + a];
    }
    if (tid < A_DIM) sAB[tid] = attn_b[tid];

    int n = row0 + tid;
    bool act = (n < N_NODES);

    float aA[A_DIM], aS[A_DIM], aD[A_DIM];
#pragma unroll
    for (int c = 0; c < A_DIM; c++) { aA[c] = 0.f; aS[c] = 0.f; aD[c] = 0.f; }

#pragma unroll 1
    for (int ch = 0; ch < 4; ch++) {
        __syncthreads();
        for (int idx = tid; idx < 2048; idx += 256) {      // 2048 float4
            int r = idx >> 3, c4 = (idx & 7) << 2;
            int n2 = row0 + r;
            if (n2 < N_NODES) {
                float4 v = __ldg(reinterpret_cast<const float4*>(
                    &x[(size_t)n2 * D_DIM + ch * 32 + c4]));
                float* d = &sx[r * XT + c4];
                d[0] = v.x; d[1] = v.y; d[2] = v.z; d[3] = v.w;
            }
        }
        __syncthreads();
        if (act) {
            const float* xr = &sx[tid * XT];
#pragma unroll
            for (int j4 = 0; j4 < 8; j4++) {
                int col = ch * 32 + j4 * 4;
                float x0 = xr[j4*4], x1 = xr[j4*4+1], x2 = xr[j4*4+2], x3 = xr[j4*4+3];
#pragma unroll
                for (int c = 0; c < A_DIM; c++) {
                    float4 wa = *reinterpret_cast<const float4*>(&shT[c * 128 + col]);
                    float4 ws = *reinterpret_cast<const float4*>(&shT[640 + c * 128 + col]);
                    float4 wd = *reinterpret_cast<const float4*>(&shT[1280 + c * 128 + col]);
                    aA[c] = fmaf(x0, wa.x, fmaf(x1, wa.y, fmaf(x2, wa.z, fmaf(x3, wa.w, aA[c]))));
                    aS[c] = fmaf(x0, ws.x, fmaf(x1, ws.y, fmaf(x2, ws.z, fmaf(x3, ws.w, aS[c]))));
                    aD[c] = fmaf(x0, wd.x, fmaf(x1, wd.y, fmaf(x2, wd.z, fmaf(x3, wd.w, aD[c]))));
                }
            }
        }
    }

    if (act) {
        float wgt[A_DIM];
        float m = -1e30f;
#pragma unroll
        for (int c = 0; c < A_DIM; c++) { wgt[c] = aA[c] + sAB[c]; m = fmaxf(m, wgt[c]); }
        float ssum = 0.f;
#pragma unroll
        for (int c = 0; c < A_DIM; c++) { wgt[c] = __expf(wgt[c] - m); ssum += wgt[c]; }
        float inv = 1.0f / ssum;
#pragma unroll
        for (int c = 0; c < A_DIM; c++) wgt[c] *= inv;

        float4 sv = {aS[0], aS[1], aS[2], aS[3]};
        float4 dv = {aD[0], aD[1], aD[2], aD[3]};
        *reinterpret_cast<float4*>(&g_s[n * 16])     = sv;
        g_s[n * 16 + 4]                              = aS[4];
        *reinterpret_cast<float4*>(&g_s[n * 16 + 8]) = dv;
        g_s[n * 16 + 12]                             = aD[4];
        float4 wv = {wgt[0], wgt[1], wgt[2], wgt[3]};
        *reinterpret_cast<float4*>(&g_wgt[(size_t)n * 8]) = wv;
        g_wgt[(size_t)n * 8 + 4]                          = wgt[4];
        float4 z = {0.f, 0.f, 0.f, 0.f};
        *reinterpret_cast<float4*>(&g_bsum[(size_t)n * 8])     = z;
        *reinterpret_cast<float4*>(&g_bsum[(size_t)n * 8 + 4]) = z;
    }
}

// ---------------------------------------------------------------------------
// Kernel 2: edge COMPUTE only — softmax b, vector REDs, store b to g_b.
// Plus the px pass (16 nodes per block). No edge_prompt store here.
// ---------------------------------------------------------------------------
__global__ __launch_bounds__(256) void edge_compute_kernel(
    const int* __restrict__ edge_index,
    const float* __restrict__ w_b,
    const float* __restrict__ x,
    const float* __restrict__ anchor_node)
{
    int tid = threadIdx.x;
    int e = blockIdx.x * 256 + tid;

    float wb[A_DIM];
#pragma unroll
    for (int c = 0; c < A_DIM; c++) wb[c] = __ldg(&w_b[c]);

    int src = edge_index[e];
    int dst = edge_index[E_EDGES + e];

    float4 s03 = *reinterpret_cast<const float4*>(&g_s[src * 16]);
    float  s4  = g_s[src * 16 + 4];
    float4 d03 = *reinterpret_cast<const float4*>(&g_s[dst * 16 + 8]);
    float  d4  = g_s[dst * 16 + 12];

    float b[A_DIM];
    b[0] = s03.x + d03.x + wb[0];
    b[1] = s03.y + d03.y + wb[1];
    b[2] = s03.z + d03.z + wb[2];
    b[3] = s03.w + d03.w + wb[3];
    b[4] = s4    + d4    + wb[4];

    float m = -1e30f;
#pragma unroll
    for (int c = 0; c < A_DIM; c++) {
        b[c] = (b[c] > 0.f) ? b[c] : 0.01f * b[c];   // leaky_relu
        m = fmaxf(m, b[c]);
    }
    float ssum = 0.f;
#pragma unroll
    for (int c = 0; c < A_DIM; c++) { b[c] = __expf(b[c] - m); ssum += b[c]; }
    float inv = 1.0f / ssum;
#pragma unroll
    for (int c = 0; c < A_DIM; c++) b[c] *= inv;

    {
        float* ps = &g_bsum[(size_t)src * 8];
        float* pd = &g_bsum[(size_t)dst * 8];
        asm volatile("red.global.add.v4.f32 [%0], {%1,%2,%3,%4};"
                     :: "l"(ps), "f"(b[0]), "f"(b[1]), "f"(b[2]), "f"(b[3]) : "memory");
        asm volatile("red.global.add.f32 [%0+16], %1;"
                     :: "l"(ps), "f"(b[4]) : "memory");
        asm volatile("red.global.add.v4.f32 [%0], {%1,%2,%3,%4};"
                     :: "l"(pd), "f"(b[0]), "f"(b[1]), "f"(b[2]), "f"(b[3]) : "memory");
        asm volatile("red.global.add.f32 [%0+16], %1;"
                     :: "l"(pd), "f"(b[4]) : "memory");
    }

    // store b for the fused store blocks
    {
        float4 b03 = {b[0], b[1], b[2], b[3]};
        *reinterpret_cast<float4*>(&g_b[(size_t)e * 8]) = b03;
        g_b[(size_t)e * 8 + 4] = b[4];
    }

    // ---- px pass: nodes [16*bid, 16*bid+16) ----
    {
        int nbase = blockIdx.x * 16;
        int c4 = (tid & 31) << 2;
        float4 a0 = __ldg(reinterpret_cast<const float4*>(&anchor_node[0 * D_DIM + c4]));
        float4 a1 = __ldg(reinterpret_cast<const float4*>(&anchor_node[1 * D_DIM + c4]));
        float4 a2 = __ldg(reinterpret_cast<const float4*>(&anchor_node[2 * D_DIM + c4]));
        float4 a3 = __ldg(reinterpret_cast<const float4*>(&anchor_node[3 * D_DIM + c4]));
        float4 a4 = __ldg(reinterpret_cast<const float4*>(&anchor_node[4 * D_DIM + c4]));
#pragma unroll
        for (int k = 0; k < 2; k++) {
            int ln = (tid >> 5) + k * 8;
            int n2 = nbase + ln;
            if (n2 < N_NODES) {
                float4 w03 = __ldg(reinterpret_cast<const float4*>(&g_wgt[(size_t)n2 * 8]));
                float  w4  = __ldg(&g_wgt[(size_t)n2 * 8 + 4]);
                float4 xv = __ldg(reinterpret_cast<const float4*>(&x[(size_t)n2 * D_DIM + c4]));
                xv.x = fmaf(w03.x,a0.x, fmaf(w03.y,a1.x, fmaf(w03.z,a2.x, fmaf(w03.w,a3.x, fmaf(w4,a4.x, xv.x)))));
                xv.y = fmaf(w03.x,a0.y, fmaf(w03.y,a1.y, fmaf(w03.z,a2.y, fmaf(w03.w,a3.y, fmaf(w4,a4.y, xv.y)))));
                xv.z = fmaf(w03.x,a0.z, fmaf(w03.y,a1.z, fmaf(w03.z,a2.z, fmaf(w03.w,a3.z, fmaf(w4,a4.z, xv.z)))));
                xv.w = fmaf(w03.x,a0.w, fmaf(w03.y,a1.w, fmaf(w03.z,a2.w, fmaf(w03.w,a3.w, fmaf(w4,a4.w, xv.w)))));
                *reinterpret_cast<float4*>(&g_node_px[(size_t)n2 * D_DIM + c4]) = xv;
            }
        }
    }
}

// ---------------------------------------------------------------------------
// Kernel 3: FUSED. Blocks [0, NPOST): node_post GEMM (R16 structure, 64 rows,
// 2 CTAs/SM, double-buffered weights). Blocks [NPOST, NPOST+3125): edge_prompt
// store blocks (read b from g_b, b@anchor_edge, streamed stores). The store
// blocks' DRAM drain overlaps the GEMM blocks' compute.
// ---------------------------------------------------------------------------
#define TMR 64
#define NPOST ((N_NODES + TMR - 1) / TMR)     // 782
#define SP  132
#define WP  136
#define SMEM_FLOATS (2 * TMR * SP + 2 * 32 * WP)
#define SMEM_BYTES  (SMEM_FLOATS * 4)

__device__ __forceinline__ void w_preload(const float* __restrict__ W, int kb,
                                          int tid, float4 w[4]) {
#pragma unroll
    for (int j = 0; j < 4; j++) {
        int i = tid + j * 256;
        int r = i >> 5, c4 = (i & 31) << 2;
        w[j] = __ldg(reinterpret_cast<const float4*>(&W[(kb + r) * 128 + c4]));
    }
}

__device__ __forceinline__ void w_commit(float* __restrict__ sW, int tid,
                                         const float4 w[4]) {
#pragma unroll
    for (int j = 0; j < 4; j++) {
        int i = tid + j * 256;
        int r = i >> 5, c4 = (i & 31) << 2;
        float4 t;
        t.x = __uint_as_float(f2tf(w[j].x));
        t.y = __uint_as_float(f2tf(w[j].y));
        t.z = __uint_as_float(f2tf(w[j].z));
        t.w = __uint_as_float(f2tf(w[j].w));
        *reinterpret_cast<float4*>(&sW[r * WP + c4]) = t;
    }
}

__device__ __forceinline__ void chunk_pt2(
    const float* __restrict__ A, int kof, const float* __restrict__ sW,
    int rbase, int nbase, int g, int tg, float acc[2][4][4])
{
#pragma unroll
    for (int ks = 0; ks < 4; ks++) {
        int k0 = ks * 8;
        uint32_t afr[2][4];
#pragma unroll
        for (int mi = 0; mi < 2; mi++) {
            const float* ap = &A[(rbase + mi * 16 + g) * SP + kof + k0 + tg];
            afr[mi][0] = __float_as_uint(ap[0]);
            afr[mi][1] = __float_as_uint(ap[8 * SP]);
            afr[mi][2] = __float_as_uint(ap[4]);
            afr[mi][3] = __float_as_uint(ap[8 * SP + 4]);
        }
        uint32_t bfr[4][2];
#pragma unroll
        for (int ni = 0; ni < 4; ni++) {
            const float* bp = &sW[(k0 + tg) * WP + nbase + ni * 8 + g];
            bfr[ni][0] = __float_as_uint(bp[0]);
            bfr[ni][1] = __float_as_uint(bp[4 * WP]);
        }
#pragma unroll
        for (int mi = 0; mi < 2; mi++)
#pragma unroll
            for (int ni = 0; ni < 4; ni++)
                mma_tf32(acc[mi][ni], afr[mi], bfr[ni]);
    }
}

__device__ __forceinline__ void chunk_sum2(
    const float* __restrict__ A0, const float* __restrict__ A1, int kof,
    const float* __restrict__ sW, int rbase, int nbase, int g, int tg,
    float acc[2][4][4])
{
#pragma unroll
    for (int ks = 0; ks < 4; ks++) {
        int k0 = ks * 8;
        uint32_t afr[2][4];
#pragma unroll
        for (int mi = 0; mi < 2; mi++) {
            int off = (rbase + mi * 16 + g) * SP + kof + k0 + tg;
            afr[mi][0] = f2tf(A0[off]            + A1[off]);
            afr[mi][1] = f2tf(A0[off + 8 * SP]   + A1[off + 8 * SP]);
            afr[mi][2] = f2tf(A0[off + 4]        + A1[off + 4]);
            afr[mi][3] = f2tf(A0[off + 8*SP + 4] + A1[off + 8*SP + 4]);
        }
        uint32_t bfr[4][2];
#pragma unroll
        for (int ni = 0; ni < 4; ni++) {
            const float* bp = &sW[(k0 + tg) * WP + nbase + ni * 8 + g];
            bfr[ni][0] = __float_as_uint(bp[0]);
            bfr[ni][1] = __float_as_uint(bp[4 * WP]);
        }
#pragma unroll
        for (int mi = 0; mi < 2; mi++)
#pragma unroll
            for (int ni = 0; ni < 4; ni++)
                mma_tf32(acc[mi][ni], afr[mi], bfr[ni]);
    }
}

__global__ __launch_bounds__(256, 2) void fused_kernel(
    const float* __restrict__ anchor_edge,
    const float* __restrict__ cd1_w, const float* __restrict__ cd1_b,
    const float* __restrict__ cd2_w, const float* __restrict__ cd2_b,
    const float* __restrict__ int_w, const float* __restrict__ int_b,
    float* __restrict__ out_final,
    float* __restrict__ out_edge)
{
    extern __shared__ float smem[];
    int tid = threadIdx.x;

    if (blockIdx.x >= NPOST) {
        // ================= edge_prompt STORE path =================
        int eb = blockIdx.x - NPOST;
        int lane = tid & 31;
        int wid  = tid >> 5;

        float4 ae[A_DIM];
#pragma unroll
        for (int c = 0; c < A_DIM; c++)
            ae[c] = __ldg(&reinterpret_cast<const float4*>(anchor_edge + c * D_DIM)[lane]);
        uint64_t aeXY[A_DIM], aeZW[A_DIM];
#pragma unroll
        for (int c = 0; c < A_DIM; c++) {
            asm("mov.b64 %0, {%1, %2};" : "=l"(aeXY[c]) : "f"(ae[c].x), "f"(ae[c].y));
            asm("mov.b64 %0, {%1, %2};" : "=l"(aeZW[c]) : "f"(ae[c].z), "f"(ae[c].w));
        }

        int e = eb * 256 + tid;
        float4 b03 = __ldg(reinterpret_cast<const float4*>(&g_b[(size_t)e * 8]));
        float  b4v = __ldg(&g_b[(size_t)e * 8 + 4]);
        float b[A_DIM] = {b03.x, b03.y, b03.z, b03.w, b4v};

        size_t ebase = (size_t)eb * 256 + wid * 32;
#pragma unroll 4
        for (int le = 0; le < 32; le++) {
            uint64_t oxy, ozw;
            {
                float bc = __shfl_sync(0xffffffffu, b[4], le);
                uint64_t bb;
                asm("mov.b64 %0, {%1, %1};" : "=l"(bb) : "f"(bc));
                asm("mul.rn.f32x2 %0, %1, %2;" : "=l"(oxy) : "l"(bb), "l"(aeXY[4]));
                asm("mul.rn.f32x2 %0, %1, %2;" : "=l"(ozw) : "l"(bb), "l"(aeZW[4]));
            }
#pragma unroll
            for (int c = 0; c < 4; c++) {
                float bc = __shfl_sync(0xffffffffu, b[c], le);
                uint64_t bb;
                asm("mov.b64 %0, {%1, %1};" : "=l"(bb) : "f"(bc));
                asm("fma.rn.f32x2 %0, %1, %2, %3;" : "=l"(oxy) : "l"(bb), "l"(aeXY[c]), "l"(oxy));
                asm("fma.rn.f32x2 %0, %1, %2, %3;" : "=l"(ozw) : "l"(bb), "l"(aeZW[c]), "l"(ozw));
            }
            float4 o;
            asm("mov.b64 {%0, %1}, %2;" : "=f"(o.x), "=f"(o.y) : "l"(oxy));
            asm("mov.b64 {%0, %1}, %2;" : "=f"(o.z), "=f"(o.w) : "l"(ozw));
            __stcs(&reinterpret_cast<float4*>(out_edge + (ebase + le) * D_DIM)[lane], o);
        }
        return;
    }

    // ================= node_post GEMM path =================
    float* sPX = smem;                  // [64][SP] tf32(px)
    float* sAG = sPX + TMR * SP;        // [64][SP] agg -> h -> final-partial
    float* sW0 = sAG + TMR * SP;        // [32][WP]
    float* sW1 = sW0 + 32 * WP;         // [32][WP]

    int row0 = blockIdx.x * TMR;

    for (int i = tid; i < TMR * 8; i += 256) {
        int n = row0 + (i >> 3);
        sW0[i] = (n < N_NODES) ? g_bsum[(size_t)n * 8 + (i & 7)] : 0.f;
    }
    for (int i = tid; i < A_DIM * D_DIM; i += 256) sW0[TMR * 8 + i] = anchor_edge[i];
    __syncthreads();

    for (int idx = tid; idx < TMR * D_DIM; idx += 256) {
        int r = idx >> 7, c = idx & 127;
        int n = row0 + r;
        float px = (n < N_NODES) ? g_node_px[(size_t)n * D_DIM + c] : 0.f;
        float ag = 0.f;
#pragma unroll
        for (int a = 0; a < A_DIM; a++)
            ag = fmaf(sW0[r * 8 + a], sW0[TMR * 8 + a * D_DIM + c], ag);
        sPX[r * SP + c] = __uint_as_float(f2tf(px));
        sAG[r * SP + c] = __uint_as_float(f2tf(ag));
    }
    __syncthreads();

    int lane = tid & 31, wid = tid >> 5;
    int wm = wid >> 2, wn = wid & 3;
    int g = lane >> 2, tg = lane & 3;
    int rbase = wm * 32;
    int nbase = wn * 32;

    float4 wreg[4];
    w_preload(int_w, 0, tid, wreg);
    w_commit(sW0, tid, wreg);
    w_preload(int_w, 32, tid, wreg);
    __syncthreads();

    float acc3[2][4][4], acc1[2][4][4], acc2[2][4][4];
#pragma unroll
    for (int mi = 0; mi < 2; mi++)
#pragma unroll
        for (int ni = 0; ni < 4; ni++)
#pragma unroll
            for (int q = 0; q < 4; q++) { acc3[mi][ni][q] = 0.f; acc1[mi][ni][q] = 0.f; acc2[mi][ni][q] = 0.f; }

#pragma unroll 1
    for (int c = 0; c < 16; c++) {
        float* bufs[2] = {sW0, sW1};
        if (c < 15) {
            w_commit(bufs[(c + 1) & 1], tid, wreg);
            int k2 = c + 2;
            if (k2 < 4)        w_preload(int_w, k2 * 32, tid, wreg);
            else if (k2 < 12)  w_preload(cd1_w, (k2 - 4) * 32, tid, wreg);
            else if (k2 < 16)  w_preload(cd2_w, (k2 - 12) * 32, tid, wreg);
        }
        const float* sWc = bufs[c & 1];
        if (c < 4)        chunk_sum2(sPX, sAG, c * 32, sWc, rbase, nbase, g, tg, acc3);
        else if (c < 8)   chunk_pt2(sPX, (c - 4) * 32, sWc, rbase, nbase, g, tg, acc1);
        else if (c < 12)  chunk_pt2(sAG, (c - 8) * 32, sWc, rbase, nbase, g, tg, acc1);
        else              chunk_pt2(sAG, (c - 12) * 32, sWc, rbase, nbase, g, tg, acc2);
        __syncthreads();

        if (c == 11) {
#pragma unroll
            for (int mi = 0; mi < 2; mi++)
#pragma unroll
                for (int ni = 0; ni < 4; ni++) {
                    int r0 = rbase + mi * 16 + g;
                    int c0 = nbase + ni * 8 + 2 * tg;
                    float b0v = cd1_b[c0], b1v = cd1_b[c0 + 1];
                    sAG[r0 * SP + c0]           = __uint_as_float(f2tf(fmaxf(acc1[mi][ni][0] + b0v, 0.f)));
                    sAG[r0 * SP + c0 + 1]       = __uint_as_float(f2tf(fmaxf(acc1[mi][ni][1] + b1v, 0.f)));
                    sAG[(r0 + 8) * SP + c0]     = __uint_as_float(f2tf(fmaxf(acc1[mi][ni][2] + b0v, 0.f)));
                    sAG[(r0 + 8) * SP + c0 + 1] = __uint_as_float(f2tf(fmaxf(acc1[mi][ni][3] + b1v, 0.f)));
                }
            __syncthreads();
        }
    }

#pragma unroll
    for (int mi = 0; mi < 2; mi++)
#pragma unroll
        for (int ni = 0; ni < 4; ni++) {
            int r0 = rbase + mi * 16 + g;
            int c0 = nbase + ni * 8 + 2 * tg;
            float bc0 = cd2_b[c0], bc1 = cd2_b[c0 + 1];
            float bi0 = int_b[c0], bi1 = int_b[c0 + 1];
#pragma unroll
            for (int h = 0; h < 2; h++) {
                int rr = r0 + h * 8;
                float cs0 = 1.0f / (1.0f + __expf(-(acc2[mi][ni][2*h]   + bc0)));
                float cs1 = 1.0f / (1.0f + __expf(-(acc2[mi][ni][2*h+1] + bc1)));
                sAG[rr * SP + c0]     = cs0 * (acc3[mi][ni][2*h]   + bi0);
                sAG[rr * SP + c0 + 1] = cs1 * (acc3[mi][ni][2*h+1] + bi1);
            }
        }
    __syncthreads();

    for (int idx = tid; idx < TMR * 32; idx += 256) {
        int r = idx >> 5, c4 = (idx & 31) << 2;
        int n = row0 + r;
        if (n < N_NODES) {
            const float* pp = &sPX[r * SP + c4];
            const float* hp = &sAG[r * SP + c4];
            float4 o = {pp[0] + hp[0], pp[1] + hp[1], pp[2] + hp[2], pp[3] + hp[3]};
            *reinterpret_cast<float4*>(&out_final[(size_t)n * D_DIM + c4]) = o;
        }
    }
}

// ---------------------------------------------------------------------------
extern "C" void kernel_launch(void* const* d_in, const int* in_sizes, int n_in,
                              void* d_out, int out_size)
{
    const float* x           = (const float*)d_in[0];
    const float* anchor_node = (const float*)d_in[1];
    const float* attn_w      = (const float*)d_in[2];
    const float* attn_b      = (const float*)d_in[3];
    const float* anchor_edge = (const float*)d_in[4];
    const float* w_w         = (const float*)d_in[5];
    const float* w_b         = (const float*)d_in[6];
    const float* cd1_w       = (const float*)d_in[7];
    const float* cd1_b       = (const float*)d_in[8];
    const float* cd2_w       = (const float*)d_in[9];
    const float* cd2_b       = (const float*)d_in[10];
    const float* int_w       = (const float*)d_in[11];
    const float* int_b       = (const float*)d_in[12];
    const int*   edge_index  = (const int*)d_in[13];
    float* outp = (float*)d_out;   // [0, N*D) = final_x, [N*D, ...) = edge_prompt

    node_pre_kernel<<<(N_NODES + 255) / 256, 256>>>(x, attn_w, attn_b, w_w);
    edge_compute_kernel<<<E_EDGES / 256, 256>>>(edge_index, w_b, x, anchor_node);
    cudaFuncSetAttribute(fused_kernel,
                         cudaFuncAttributeMaxDynamicSharedMemorySize, SMEM_BYTES);
    fused_kernel<<<NPOST + E_EDGES / 256, 256, SMEM_BYTES>>>(
        anchor_edge, cd1_w, cd1_b, cd2_w, cd2_b, int_w, int_b,
        outp, outp + (size_t)N_NODES * D_DIM);
}